// round 1
// baseline (speedup 1.0000x reference)
#include <cuda_runtime.h>
#include <math.h>

#define D    128
#define TM   128      // rows per CTA
#define TKC  64       // centers per smem tile
#define SFS  132      // sf row stride in floats (16B-aligned, padded)
#define EPSF 1e-12f
#define KMAX 2048

// Scratch (no allocations allowed)
__device__ float  g_chat[KMAX * D];   // normalized centers
__device__ float  g_cnorm[KMAX];      // ||c||
__device__ float  g_cnorm2[KMAX];     // ||c||^2
__device__ double g_sum;

// ---------------------------------------------------------------------------
// Kernel A: normalize centers, record norms; block 0 zeroes the accumulator.
// grid = K blocks, 128 threads (one per dim)
// ---------------------------------------------------------------------------
__global__ void prep_centers_kernel(const float* __restrict__ centers) {
    int k = blockIdx.x;
    int t = threadIdx.x;

    float v = centers[(size_t)k * D + t];
    float s = v * v;
    #pragma unroll
    for (int o = 16; o; o >>= 1) s += __shfl_xor_sync(0xffffffffu, s, o);

    __shared__ float ws[4];
    __shared__ float n2s;
    if ((t & 31) == 0) ws[t >> 5] = s;
    __syncthreads();
    if (t == 0) {
        float n2 = ws[0] + ws[1] + ws[2] + ws[3];
        n2s = n2;
        float n = sqrtf(n2);
        g_cnorm[k]  = n;
        g_cnorm2[k] = n2;
        if (k == 0) g_sum = 0.0;   // runs before main kernel (same stream)
    }
    __syncthreads();

    float n    = sqrtf(n2s);
    float rinv = 1.0f / fmaxf(n, EPSF);
    g_chat[(size_t)k * D + t] = v * rinv;
}

// ---------------------------------------------------------------------------
// Kernel B: fused normalize(features) + GEMM + argmax + loss partial sums.
// 128 threads, TM=128 rows per CTA. Thread (cx = tid&7, rg = tid>>3) computes
// an 8-row x 8-center micro-tile; its 8 centers in each 64-center tile are
// {cx*4..cx*4+3} and {32+cx*4..32+cx*4+3} (keeps LDS.128 fetches 1-phase).
// ---------------------------------------------------------------------------
__global__ void __launch_bounds__(128, 2) cluster_main_kernel(
    const float* __restrict__ features, int N, int K)
{
    extern __shared__ float smem[];
    float* sf     = smem;                    // TM*SFS
    float* sc     = sf + TM * SFS;           // D*TKC, layout [d][c]
    float* snorm2 = sc + D * TKC;            // TM
    float* srinv  = snorm2 + TM;             // TM
    float* sfn2   = srinv + TM;              // TM
    float* spart  = sfn2 + TM;               // 16

    const int tid  = threadIdx.x;
    const int lane = tid & 31;
    const int warp = tid >> 5;
    const int row0 = blockIdx.x * TM;

    // ---- load features tile (coalesced: one warp loads one full row/iter),
    //      computing row sum-of-squares on the fly ----
    #pragma unroll 4
    for (int it = 0; it < TM / 4; ++it) {
        int r = warp + 4 * it;
        float4 v = *(const float4*)(features + (size_t)(row0 + r) * D + lane * 4);
        *(float4*)(sf + r * SFS + lane * 4) = v;
        float s = v.x * v.x + v.y * v.y + v.z * v.z + v.w * v.w;
        #pragma unroll
        for (int o = 16; o; o >>= 1) s += __shfl_xor_sync(0xffffffffu, s, o);
        if (lane == 0) snorm2[r] = s;
    }
    __syncthreads();

    if (tid < TM) {
        float n2 = snorm2[tid];
        float n  = sqrtf(n2);
        float ri = 1.0f / fmaxf(n, EPSF);
        srinv[tid] = ri;
        sfn2[tid]  = n2 * ri * ri;   // ||f_hat||^2 (== 1 up to rounding)
    }
    __syncthreads();

    // ---- normalize rows in smem ----
    #pragma unroll 4
    for (int it = 0; it < TM / 4; ++it) {
        int r = warp + 4 * it;
        float ri = srinv[r];
        float4* p = (float4*)(sf + r * SFS + lane * 4);
        float4 v = *p;
        v.x *= ri; v.y *= ri; v.z *= ri; v.w *= ri;
        *p = v;
    }
    __syncthreads();

    const int cx = tid & 7;    // column-lane
    const int rg = tid >> 3;   // row group (0..15)
    const int rbase = rg * 8;

    float best_v[8];
    int   best_i[8];
    #pragma unroll
    for (int i = 0; i < 8; ++i) { best_v[i] = -INFINITY; best_i[i] = 0; }

    const int ntile = K / TKC;
    for (int kt = 0; kt < ntile; ++kt) {
        const int k0 = kt * TKC;

        // load center tile transposed into sc[d][c] (conflict-free STS)
        #pragma unroll 4
        for (int it = 0; it < 16; ++it) {
            int i  = tid + 128 * it;
            int c  = i & 63;
            int dq = i >> 6;    // 0..31
            float4 v = *(const float4*)(g_chat + (size_t)(k0 + c) * D + dq * 4);
            sc[(dq * 4 + 0) * TKC + c] = v.x;
            sc[(dq * 4 + 1) * TKC + c] = v.y;
            sc[(dq * 4 + 2) * TKC + c] = v.z;
            sc[(dq * 4 + 3) * TKC + c] = v.w;
        }
        __syncthreads();

        float acc[8][8];
        #pragma unroll
        for (int i = 0; i < 8; ++i)
            #pragma unroll
            for (int j = 0; j < 8; ++j) acc[i][j] = 0.0f;

        #pragma unroll 2
        for (int d = 0; d < D; d += 4) {
            float4 fv[8];
            #pragma unroll
            for (int i = 0; i < 8; ++i)
                fv[i] = *(const float4*)(sf + (rbase + i) * SFS + d);
            #pragma unroll
            for (int dd = 0; dd < 4; ++dd) {
                float4 ca = *(const float4*)(sc + (d + dd) * TKC + cx * 4);
                float4 cb = *(const float4*)(sc + (d + dd) * TKC + 32 + cx * 4);
                #pragma unroll
                for (int i = 0; i < 8; ++i) {
                    float f = (dd == 0) ? fv[i].x : (dd == 1) ? fv[i].y
                            : (dd == 2) ? fv[i].z : fv[i].w;
                    acc[i][0] = fmaf(f, ca.x, acc[i][0]);
                    acc[i][1] = fmaf(f, ca.y, acc[i][1]);
                    acc[i][2] = fmaf(f, ca.z, acc[i][2]);
                    acc[i][3] = fmaf(f, ca.w, acc[i][3]);
                    acc[i][4] = fmaf(f, cb.x, acc[i][4]);
                    acc[i][5] = fmaf(f, cb.y, acc[i][5]);
                    acc[i][6] = fmaf(f, cb.z, acc[i][6]);
                    acc[i][7] = fmaf(f, cb.w, acc[i][7]);
                }
            }
        }
        __syncthreads();   // before next tile's sc overwrite

        // fold this tile into the running argmax
        #pragma unroll
        for (int i = 0; i < 8; ++i) {
            #pragma unroll
            for (int j = 0; j < 8; ++j) {
                int cidx = k0 + ((j < 4) ? (cx * 4 + j) : (32 + cx * 4 + (j - 4)));
                float v = acc[i][j];
                if (v > best_v[i] || (v == best_v[i] && cidx < best_i[i])) {
                    best_v[i] = v; best_i[i] = cidx;
                }
            }
        }
    }

    // reduce argmax across the 8 column-lanes sharing the same rows
    #pragma unroll
    for (int o = 4; o; o >>= 1) {
        #pragma unroll
        for (int i = 0; i < 8; ++i) {
            float ov = __shfl_down_sync(0xffffffffu, best_v[i], o, 8);
            int   oi = __shfl_down_sync(0xffffffffu, best_i[i], o, 8);
            if (ov > best_v[i] || (ov == best_v[i] && oi < best_i[i])) {
                best_v[i] = ov; best_i[i] = oi;
            }
        }
    }

    if (cx == 0) {
        float lsum = 0.0f;
        #pragma unroll
        for (int i = 0; i < 8; ++i) {
            int   r  = rbase + i;
            int   bi = best_i[i];
            float bv = best_v[i];
            // ||f_hat - c||^2 = ||f_hat||^2 - 2*sim*||c|| + ||c||^2
            lsum += sfn2[r] - 2.0f * bv * g_cnorm[bi] + g_cnorm2[bi];
        }
        spart[rg] = lsum;
    }
    __syncthreads();
    if (tid == 0) {
        float bs = 0.0f;
        #pragma unroll
        for (int i = 0; i < 16; ++i) bs += spart[i];
        atomicAdd(&g_sum, (double)bs);
    }
}

// ---------------------------------------------------------------------------
// Kernel C: finalize mean
// ---------------------------------------------------------------------------
__global__ void finalize_kernel(float* out, int N) {
    out[0] = (float)(g_sum / (double)N);
}

extern "C" void kernel_launch(void* const* d_in, const int* in_sizes, int n_in,
                              void* d_out, int out_size) {
    const float* features = (const float*)d_in[0];
    const float* centers  = (const float*)d_in[1];
    int N = in_sizes[0] / D;
    int K = in_sizes[1] / D;

    const int smem_bytes = (TM * SFS + D * TKC + 3 * TM + 16) * (int)sizeof(float);
    cudaFuncSetAttribute(cluster_main_kernel,
                         cudaFuncAttributeMaxDynamicSharedMemorySize, smem_bytes);

    prep_centers_kernel<<<K, 128>>>(centers);
    cluster_main_kernel<<<N / TM, 128, smem_bytes>>>(features, N, K);
    finalize_kernel<<<1, 1>>>((float*)d_out, N);
}

// round 6
// speedup vs baseline: 5.3859x; 5.3859x over previous
#include <cuda_runtime.h>
#include <cuda_bf16.h>
#include <math.h>
#include <stdint.h>

#define DDIM  128
#define MC    256          // rows per CTA
#define NB    128          // centers per B tile
#define NTILE 8            // K / NB
#define KCENT 1024
#define EPSF  1e-12f
#define THREADS 512

// ---------------- device scratch (no allocations allowed) -------------------
__device__ __nv_bfloat16 g_cbf[KCENT * DDIM];   // normalized centers, bf16
__device__ double g_sum;

// ---------------- helpers ---------------------------------------------------
__device__ __forceinline__ uint32_t smem_u32(const void* p) {
    uint32_t a;
    asm("{ .reg .u64 t; cvta.to.shared.u64 t, %1; cvt.u32.u64 %0, t; }"
        : "=r"(a) : "l"(p));
    return a;
}
__device__ __forceinline__ void cpa16(uint32_t dst, const void* src) {
    asm volatile("cp.async.cg.shared.global [%0], [%1], 16;"
                 :: "r"(dst), "l"(src));
}
__device__ __forceinline__ void cpa_commit() {
    asm volatile("cp.async.commit_group;" ::: "memory");
}
__device__ __forceinline__ void cpa_wait0() {
    asm volatile("cp.async.wait_group 0;" ::: "memory");
}
__device__ __forceinline__ void ldsm_x4(uint32_t* r, uint32_t addr) {
    asm volatile("ldmatrix.sync.aligned.m8n8.x4.shared.b16 {%0,%1,%2,%3}, [%4];"
                 : "=r"(r[0]), "=r"(r[1]), "=r"(r[2]), "=r"(r[3]) : "r"(addr));
}
__device__ __forceinline__ void mma16816(float* d, const uint32_t* a,
                                         const uint32_t* b) {
    asm volatile(
        "mma.sync.aligned.m16n8k16.row.col.f32.bf16.bf16.f32 "
        "{%0,%1,%2,%3}, {%4,%5,%6,%7}, {%8,%9}, {%0,%1,%2,%3};"
        : "+f"(d[0]), "+f"(d[1]), "+f"(d[2]), "+f"(d[3])
        : "r"(a[0]), "r"(a[1]), "r"(a[2]), "r"(a[3]), "r"(b[0]), "r"(b[1]));
}
__device__ __forceinline__ uint32_t pack_bf2(float a, float b) {
    __nv_bfloat16 ha = __float2bfloat16(a);
    __nv_bfloat16 hb = __float2bfloat16(b);
    return (uint32_t)__bfloat16_as_ushort(ha)
         | ((uint32_t)__bfloat16_as_ushort(hb) << 16);
}
// row-major bf16 tile, 256B rows (16 x 16B chunks), XOR-8 swizzle
__device__ __forceinline__ uint32_t swz(uint32_t row, uint32_t chunk) {
    return row * 256u + ((chunk ^ (row & 7u)) << 4);
}

// ---------------------------------------------------------------------------
// Kernel A: normalize centers -> bf16 row-major; zero accumulator.
// grid = K blocks x 128 threads (thread = dim)
// ---------------------------------------------------------------------------
__global__ void prep_centers_kernel(const float* __restrict__ centers) {
    int k = blockIdx.x;
    int t = threadIdx.x;

    float v = centers[(size_t)k * DDIM + t];
    float s = v * v;
    #pragma unroll
    for (int o = 16; o; o >>= 1) s += __shfl_xor_sync(0xffffffffu, s, o);

    __shared__ float ws[4];
    __shared__ float n2s;
    if ((t & 31) == 0) ws[t >> 5] = s;
    __syncthreads();
    if (t == 0) {
        n2s = ws[0] + ws[1] + ws[2] + ws[3];
        if (k == 0) g_sum = 0.0;
    }
    __syncthreads();

    float ri = 1.0f / fmaxf(sqrtf(n2s), EPSF);
    g_cbf[(size_t)k * DDIM + t] = __float2bfloat16(v * ri);
}

// ---------------------------------------------------------------------------
// Kernel B: bf16 mma.sync GEMM (sims) + fused argmax + exact fp32 loss.
// 512 threads, 256 rows/CTA. Warp tile 32(m) x 64(n); warps 8(m) x 2(n).
// ---------------------------------------------------------------------------
__global__ void __launch_bounds__(THREADS, 1) cluster_main_kernel(
    const float* __restrict__ features,
    const float* __restrict__ centers, int N)
{
    extern __shared__ char dsm[];
    // layout: A (64KB) | B[2] (64KB) | s_ri (1KB) | s_best (1KB) | spart
    const uint32_t Ab = smem_u32(dsm);
    const uint32_t Bb = Ab + 65536u;
    float* s_ri   = (float*)(dsm + 131072);
    int*   s_best = (int*)  (dsm + 131072 + 1024);
    float* spart  = (float*)(dsm + 131072 + 2048);

    const int tid  = threadIdx.x;
    const int lane = tid & 31;
    const int w    = tid >> 5;          // 0..15
    const int row0 = blockIdx.x * MC;

    // ---- kick off B tile 0 load ----
    {
        const char* src = (const char*)g_cbf;
        #pragma unroll
        for (int j = tid; j < 2048; j += THREADS) {
            int n = j >> 4, c = j & 15;
            cpa16(Bb + swz(n, c), src + n * 256 + c * 16);
        }
        cpa_commit();
    }

    // ---- phase 1: load 256 feature rows, normalize, bf16 -> smem A ----
    #pragma unroll 4
    for (int i = 0; i < 16; ++i) {
        int r = 16 * w + i;
        float4 v = *(const float4*)(features + (size_t)(row0 + r) * DDIM
                                    + 4 * lane);
        float s = v.x * v.x + v.y * v.y + v.z * v.z + v.w * v.w;
        #pragma unroll
        for (int o = 16; o; o >>= 1) s += __shfl_xor_sync(0xffffffffu, s, o);
        float ri = 1.0f / fmaxf(sqrtf(s), EPSF);
        if (lane == 0) s_ri[r] = ri;
        uint32_t p0 = pack_bf2(v.x * ri, v.y * ri);
        uint32_t p1 = pack_bf2(v.z * ri, v.w * ri);
        uint32_t addr = Ab + swz(r, lane >> 1) + (lane & 1) * 8;
        asm volatile("st.shared.v2.b32 [%0], {%1,%2};"
                     :: "r"(addr), "r"(p0), "r"(p1));
    }
    __syncthreads();

    // ---- warp tiling ----
    const int wm = w & 7, wn = w >> 3;
    const int rb = 32 * wm;          // warp row base
    const int nb0 = 64 * wn;         // warp col base within tile

    float best_v[4];
    int   best_i[4];
    #pragma unroll
    for (int s = 0; s < 4; ++s) { best_v[s] = -INFINITY; best_i[s] = 0; }

    #pragma unroll 1
    for (int t = 0; t < NTILE; ++t) {
        cpa_wait0();
        __syncthreads();
        const uint32_t Bt = Bb + (uint32_t)(t & 1) * 32768u;

        if (t < NTILE - 1) {   // prefetch next tile into other buffer
            const char* src = (const char*)(g_cbf + (size_t)(t + 1) * NB * DDIM);
            uint32_t dst = Bb + (uint32_t)((t + 1) & 1) * 32768u;
            #pragma unroll
            for (int j = tid; j < 2048; j += THREADS) {
                int n = j >> 4, c = j & 15;
                cpa16(dst + swz(n, c), src + n * 256 + c * 16);
            }
            cpa_commit();
        }

        float acc[2][8][4];
        #pragma unroll
        for (int a = 0; a < 2; ++a)
            #pragma unroll
            for (int b = 0; b < 8; ++b)
                #pragma unroll
                for (int e = 0; e < 4; ++e) acc[a][b][e] = 0.0f;

        #pragma unroll
        for (int ks = 0; ks < 8; ++ks) {
            uint32_t a0[4], a1[4];
            {
                int row = rb + (lane & 15);
                int ch  = 2 * ks + (lane >> 4);
                ldsm_x4(a0, Ab + swz(row, ch));
                ldsm_x4(a1, Ab + swz(row + 16, ch));
            }
            uint32_t bfr[8][2];
            #pragma unroll
            for (int g = 0; g < 4; ++g) {
                int n  = nb0 + 16 * g + (lane & 7) + ((lane >> 4) << 3);
                int ch = 2 * ks + ((lane >> 3) & 1);
                uint32_t r4[4];
                ldsm_x4(r4, Bt + swz(n, ch));
                bfr[2 * g][0] = r4[0]; bfr[2 * g][1] = r4[1];
                bfr[2 * g + 1][0] = r4[2]; bfr[2 * g + 1][1] = r4[3];
            }
            #pragma unroll
            for (int nt = 0; nt < 8; ++nt) {
                mma16816(acc[0][nt], a0, bfr[nt]);
                mma16816(acc[1][nt], a1, bfr[nt]);
            }
        }
        __syncthreads();   // all warps done reading Bt before it is refilled

        // fold argmax: slot s = 2*mt + rh; rows rb + 16*mt + (lane>>2) + 8*rh
        const int kbase = t * NB + nb0 + 2 * (lane & 3);
        #pragma unroll
        for (int mt = 0; mt < 2; ++mt) {
            #pragma unroll
            for (int rh = 0; rh < 2; ++rh) {
                int s = 2 * mt + rh;
                #pragma unroll
                for (int nt = 0; nt < 8; ++nt) {
                    float v0 = acc[mt][nt][2 * rh];
                    float v1 = acc[mt][nt][2 * rh + 1];
                    int   i0 = kbase + 8 * nt;
                    if (v0 > best_v[s]) { best_v[s] = v0; best_i[s] = i0; }
                    if (v1 > best_v[s]) { best_v[s] = v1; best_i[s] = i0 + 1; }
                }
            }
        }
    }

    // ---- reduce argmax over the 4 lanes of each quad ----
    #pragma unroll
    for (int off = 1; off < 4; off <<= 1) {
        #pragma unroll
        for (int s = 0; s < 4; ++s) {
            float ov = __shfl_down_sync(0xffffffffu, best_v[s], off);
            int   oi = __shfl_down_sync(0xffffffffu, best_i[s], off);
            if (ov > best_v[s] || (ov == best_v[s] && oi < best_i[s])) {
                best_v[s] = ov; best_i[s] = oi;
            }
        }
    }
    if ((lane & 3) == 0) {
        int q = lane >> 2;
        #pragma unroll
        for (int s = 0; s < 4; ++s) {
            int mt = s >> 1, rh = s & 1;
            s_best[rb + 16 * mt + 8 * rh + q] = best_i[s];
        }
    }
    __syncthreads();

    // ---- phase 3: exact fp32 loss for assigned center ----
    float ls = 0.0f;
    if (tid < MC) {
        int r = tid;
        float ri = s_ri[r];
        int bi = s_best[r];
        const float4* fp = (const float4*)(features + (size_t)(row0 + r) * DDIM);
        const float4* cp = (const float4*)(centers + (size_t)bi * DDIM);
        #pragma unroll 8
        for (int j = 0; j < 32; ++j) {
            float4 f = fp[j], c = cp[j];
            float dx = fmaf(f.x, ri, -c.x);
            float dy = fmaf(f.y, ri, -c.y);
            float dz = fmaf(f.z, ri, -c.z);
            float dw = fmaf(f.w, ri, -c.w);
            ls += dx * dx + dy * dy + dz * dz + dw * dw;
        }
    }
    #pragma unroll
    for (int o = 16; o; o >>= 1) ls += __shfl_xor_sync(0xffffffffu, ls, o);
    if (lane == 0) spart[w] = ls;
    __syncthreads();
    if (tid == 0) {
        float bs = 0.0f;
        #pragma unroll
        for (int i = 0; i < 8; ++i) bs += spart[i];   // warps 8..15 had tid>=256
        atomicAdd(&g_sum, (double)bs);
    }
}

// ---------------------------------------------------------------------------
__global__ void finalize_kernel(float* out, int N) {
    out[0] = (float)(g_sum / (double)N);
}

extern "C" void kernel_launch(void* const* d_in, const int* in_sizes, int n_in,
                              void* d_out, int out_size) {
    const float* features = (const float*)d_in[0];
    const float* centers  = (const float*)d_in[1];
    int N = in_sizes[0] / DDIM;
    int K = in_sizes[1] / DDIM;
    (void)K;

    const int smem_bytes = 131072 + 2048 + 64 * 4;
    cudaFuncSetAttribute(cluster_main_kernel,
                         cudaFuncAttributeMaxDynamicSharedMemorySize, smem_bytes);

    prep_centers_kernel<<<KCENT, 128>>>(centers);
    cluster_main_kernel<<<N / MC, THREADS, smem_bytes>>>(features, centers, N);
    finalize_kernel<<<1, 1>>>((float*)d_out, N);
}